// round 15
// baseline (speedup 1.0000x reference)
#include <cuda_runtime.h>
#include <math.h>
#include <stdint.h>

#define BB 2
#define SS 2048
#define DD 2304
#define NHQ 8
#define NHKV 4
#define HD 256
#define FF 9216
#define MM (BB*SS)   // 4096 rows

// ---------------- persistent scratch (no allocations allowed) ----------------
__device__ float g_x  [MM*DD];
__device__ float g_h  [MM*DD];
__device__ float g_qkv[MM*4096];          // q (0..2047) | k (2048..3071) | v (3072..4095)
__device__ float g_att[MM*NHQ*HD];
__device__ float g_tmp[MM*DD];
__device__ float g_ff [MM*FF];
__device__ float g_ff2[MM*FF];
// pre-rounded (tf32) weights
__device__ uint32_t g_wqkv[DD*4096];
__device__ uint32_t g_wo [NHQ*HD*DD];
__device__ uint32_t g_wi0[DD*FF];
__device__ uint32_t g_wi1[DD*FF];
__device__ uint32_t g_wom[FF*DD];

__device__ __forceinline__ uint32_t f2tf(float x) {
    uint32_t r;
    asm("cvt.rna.tf32.f32 %0, %1;" : "=r"(r) : "f"(x));
    return r;
}

// ---------------- small helpers ----------------
__global__ void copy_kernel(float* __restrict__ dst, const float* __restrict__ src, int n) {
    int i = blockIdx.x * blockDim.x + threadIdx.x;
    if (i < n) dst[i] = src[i];
}

// tf32-round and (optionally) pack into a wider matrix at column offset.
// Works in float4 units. src is [n4/ncols4_src rows, ncols4_src cols4].
__global__ void round_pack_kernel(const float4* __restrict__ in, uint4* __restrict__ out,
                                  int ncols4_src, int ncols4_dst, int col0_4, int n4) {
    int i = blockIdx.x * blockDim.x + threadIdx.x;
    if (i >= n4) return;
    int k = i / ncols4_src, j = i - k * ncols4_src;
    float4 v = in[i];
    uint4 u;
    u.x = f2tf(v.x); u.y = f2tf(v.y); u.z = f2tf(v.z); u.w = f2tf(v.w);
    out[(size_t)k * ncols4_dst + col0_4 + j] = u;
}

// out[row] = tf32_round(in[row] * rsqrt(mean(in^2)+eps) * scale)   (GEMM A operand)
__global__ void rms_kernel(const float* __restrict__ in, const float* __restrict__ scale,
                           float* __restrict__ out) {
    int row = blockIdx.x;
    const float* r = in + (size_t)row * DD;
    float ss = 0.f;
    for (int i = threadIdx.x; i < DD; i += 256) { float v = r[i]; ss += v * v; }
    #pragma unroll
    for (int o = 16; o; o >>= 1) ss += __shfl_xor_sync(0xffffffffu, ss, o);
    __shared__ float red[8];
    if ((threadIdx.x & 31) == 0) red[threadIdx.x >> 5] = ss;
    __syncthreads();
    float tot = red[0]+red[1]+red[2]+red[3]+red[4]+red[5]+red[6]+red[7];
    float rs = rsqrtf(tot / (float)DD + 1e-6f);
    float* o = out + (size_t)row * DD;
    for (int i = threadIdx.x; i < DD; i += 256)
        o[i] = __uint_as_float(f2tf(r[i] * rs * scale[i]));
}

__global__ void rms_add_kernel(const float* __restrict__ a, const float* __restrict__ scale,
                               float* __restrict__ x) {
    int row = blockIdx.x;
    const float* r = a + (size_t)row * DD;
    float ss = 0.f;
    for (int i = threadIdx.x; i < DD; i += 256) { float v = r[i]; ss += v * v; }
    #pragma unroll
    for (int o = 16; o; o >>= 1) ss += __shfl_xor_sync(0xffffffffu, ss, o);
    __shared__ float red[8];
    if ((threadIdx.x & 31) == 0) red[threadIdx.x >> 5] = ss;
    __syncthreads();
    float tot = red[0]+red[1]+red[2]+red[3]+red[4]+red[5]+red[6]+red[7];
    float rs = rsqrtf(tot / (float)DD + 1e-6f);
    float* xo = x + (size_t)row * DD;
    for (int i = threadIdx.x; i < DD; i += 256) xo[i] += r[i] * rs * scale[i];
}

__device__ __forceinline__ float gelu_tanh(float x) {
    float x3 = x * x * x;
    return 0.5f * x * (1.f + tanhf(0.7978845608028654f * (x + 0.044715f * x3)));
}

// ---------------- tf32 tensor-core GEMM, cp.async 3-stage pipeline ----------------
#define GSTAGES 3
#define SMEM_GEMM (GSTAGES * (128*32 + 32*128) * 4)

__device__ __forceinline__ void mma8(float* c, const uint32_t* a, const uint32_t* b) {
    asm volatile("mma.sync.aligned.m16n8k8.row.col.f32.tf32.tf32.f32 "
        "{%0,%1,%2,%3},{%4,%5,%6,%7},{%8,%9},{%0,%1,%2,%3};"
        : "+f"(c[0]), "+f"(c[1]), "+f"(c[2]), "+f"(c[3])
        : "r"(a[0]), "r"(a[1]), "r"(a[2]), "r"(a[3]), "r"(b[0]), "r"(b[1]));
}

template<int MODE>
__global__ void __launch_bounds__(256) tf32_gemm(const uint32_t* __restrict__ A,
                                                 const uint32_t* __restrict__ B,
                                                 float* __restrict__ C,
                                                 const float* __restrict__ aux,
                                                 int M, int N, int K, float alpha) {
    extern __shared__ uint32_t smem_[];
    uint32_t* As = smem_;                          // [GSTAGES][128*32], col ^ 4*(row&7)
    uint32_t* Bs = smem_ + GSTAGES * 128 * 32;     // [GSTAGES][32*128], col ^ 8*(row&3)

    int tid = threadIdx.x;
    int lane = tid & 31;
    int warp = tid >> 5;
    int wm = warp & 3;
    int wn = warp >> 2;
    int g = lane >> 2;
    int t = lane & 3;

    int m0 = blockIdx.y * 128;
    int n0 = blockIdx.x * 128;

    int arow = tid >> 3;            // 0..31
    int acol = (tid & 7) * 4;       // 0..28
    int brow = tid >> 5;            // 0..7
    int bcol = (tid & 31) * 4;      // 0..124

    float acc[2][8][4];
    #pragma unroll
    for (int mi = 0; mi < 2; mi++)
        #pragma unroll
        for (int ni = 0; ni < 8; ni++)
            #pragma unroll
            for (int j = 0; j < 4; j++) acc[mi][ni][j] = 0.f;

    auto load_stage = [&](int k0, int s) {
        uint32_t* Ad = As + s * (128 * 32);
        uint32_t* Bd = Bs + s * (32 * 128);
        #pragma unroll
        for (int p = 0; p < 4; p++) {
            int r = arow + p * 32;
            int sc = acol ^ (4 * (r & 7));
            uint32_t d = (uint32_t)__cvta_generic_to_shared(Ad + r * 32 + sc);
            asm volatile("cp.async.cg.shared.global [%0], [%1], 16;\n"
                         :: "r"(d), "l"(A + (size_t)(m0 + r) * K + k0 + acol));
        }
        #pragma unroll
        for (int p = 0; p < 4; p++) {
            int r = brow + p * 8;
            int sc = bcol ^ (8 * (r & 3));
            uint32_t d = (uint32_t)__cvta_generic_to_shared(Bd + r * 128 + sc);
            asm volatile("cp.async.cg.shared.global [%0], [%1], 16;\n"
                         :: "r"(d), "l"(B + (size_t)(k0 + r) * N + n0 + bcol));
        }
    };

    int nk = K / 32;
    load_stage(0, 0);
    asm volatile("cp.async.commit_group;\n" ::);
    load_stage(32, 1);
    asm volatile("cp.async.commit_group;\n" ::);

    for (int ki = 0; ki < nk; ki++) {
        asm volatile("cp.async.wait_group 1;\n" ::);
        __syncthreads();
        if (ki + 2 < nk) load_stage((ki + 2) * 32, (ki + 2) % GSTAGES);
        asm volatile("cp.async.commit_group;\n" ::);

        const uint32_t* Ac = As + (ki % GSTAGES) * (128 * 32);
        const uint32_t* Bc = Bs + (ki % GSTAGES) * (32 * 128);

        #pragma unroll
        for (int kk = 0; kk < 32; kk += 8) {
            uint32_t af[2][4], bf[8][2];
            #pragma unroll
            for (int mi = 0; mi < 2; mi++) {
                int r0 = wm * 32 + mi * 16 + g;
                int c0 = (kk + t) ^ (4 * g);
                int c1 = (kk + t + 4) ^ (4 * g);
                af[mi][0] = Ac[r0 * 32 + c0];
                af[mi][1] = Ac[(r0 + 8) * 32 + c0];
                af[mi][2] = Ac[r0 * 32 + c1];
                af[mi][3] = Ac[(r0 + 8) * 32 + c1];
            }
            #pragma unroll
            for (int ni = 0; ni < 8; ni++) {
                int n = wn * 64 + ni * 8 + g;
                bf[ni][0] = Bc[(kk + t) * 128 + (n ^ (8 * t))];
                bf[ni][1] = Bc[(kk + t + 4) * 128 + (n ^ (8 * t))];
            }
            #pragma unroll
            for (int mi = 0; mi < 2; mi++)
                #pragma unroll
                for (int ni = 0; ni < 8; ni++)
                    mma8(acc[mi][ni], af[mi], bf[ni]);
        }
    }

    #pragma unroll
    for (int mi = 0; mi < 2; mi++) {
        #pragma unroll
        for (int ni = 0; ni < 8; ni++) {
            int row = m0 + wm * 32 + mi * 16 + g;
            int col = n0 + wn * 64 + ni * 8 + 2 * t;
            size_t i0 = (size_t)row * N + col;
            size_t i1 = (size_t)(row + 8) * N + col;
            if (MODE == 0) {
                float2 v0 = make_float2(acc[mi][ni][0] * alpha, acc[mi][ni][1] * alpha);
                float2 v1 = make_float2(acc[mi][ni][2] * alpha, acc[mi][ni][3] * alpha);
                *(float2*)(C + i0) = v0;
                *(float2*)(C + i1) = v1;
            } else {
                float2 a0 = *(const float2*)(aux + i0);
                float2 a1 = *(const float2*)(aux + i1);
                float2 v0 = make_float2(__uint_as_float(f2tf(gelu_tanh(a0.x) * acc[mi][ni][0])),
                                        __uint_as_float(f2tf(gelu_tanh(a0.y) * acc[mi][ni][1])));
                float2 v1 = make_float2(__uint_as_float(f2tf(gelu_tanh(a1.x) * acc[mi][ni][2])),
                                        __uint_as_float(f2tf(gelu_tanh(a1.y) * acc[mi][ni][3])));
                *(float2*)(C + i0) = v0;
                *(float2*)(C + i1) = v1;
            }
        }
    }
}

// ---------------- RoPE on merged qkv (q heads 0..7 at col h*256, k heads at 2048+h*256) ----------------
__global__ void rope_merged_kernel(float* __restrict__ qkv, const int* __restrict__ positions, int total) {
    int idx = blockIdx.x * blockDim.x + threadIdx.x;
    if (idx >= total) return;
    int i = idx & 127;
    int hh = (idx >> 7) % 12;                // 0..7 = q heads, 8..11 = k heads
    int row = idx / (128 * 12);              // 0..MM-1
    int s = row % SS, b = row / SS;
    int p = positions[b * SS + s];
    double f = exp2(-(double)i * (13.287712379549449 / 128.0));
    double ang = (double)p * f;
    double sd, cd;
    sincos(ang, &sd, &cd);
    float sn = (float)sd, cs = (float)cd;
    int col = (hh < 8) ? hh * 256 : 2048 + (hh - 8) * 256;
    float* base = qkv + (size_t)row * 4096 + col;
    float x1 = base[i], x2 = base[128 + i];
    base[i]       = x1 * cs - x2 * sn;
    base[128 + i] = x2 * cs + x1 * sn;
}

// ---------------- attention: online softmax, softcap, causal+window+segment ----------------
// KPAD=260: float4 row loads are conflict-free (8-lane phases x 4 words cover all 32 banks),
// and rows stay 16B-aligned (260*4 = 1040 = 65*16).
#define KPAD 260
#define ATTN_SMEM_FLOATS (32*256 + 32*KPAD + 32*KPAD + 8*4*32 + 64)
#define ATTN_SMEM_BYTES (ATTN_SMEM_FLOATS * 4)

__global__ void __launch_bounds__(256) attn_kernel(const float* __restrict__ qkv,
                                                   const int* __restrict__ pos,
                                                   const int* __restrict__ seg,
                                                   float* __restrict__ out,
                                                   int window) {
    extern __shared__ float sm[];
    float* Qs = sm;                      // [32][256]
    float* Ks = Qs + 32 * 256;           // [32][KPAD]
    float* Vs = Ks + 32 * KPAD;          // [32][KPAD]
    float* Ps = Vs + 32 * KPAD;          // [8][4][32]
    int* kposs = (int*)(Ps + 8 * 4 * 32);
    int* ksegs = kposs + 32;

    int b = blockIdx.z, h = blockIdx.y, qt = blockIdx.x;
    int kvh = h / (NHQ / NHKV);
    int tid = threadIdx.x, w = tid >> 5, lane = tid & 31;
    int q0g = qt * 32;

    // load Q tile (float4)
    for (int t = tid; t < 32 * 64; t += 256) {
        int lq = t >> 6, d4 = t & 63;
        *(float4*)(Qs + lq * 256 + 4 * d4) =
            *(const float4*)(qkv + (size_t)(b * SS + q0g + lq) * 4096 + h * 256 + 4 * d4);
    }

    int qp[4], qsg[4];
    #pragma unroll
    for (int qi = 0; qi < 4; qi++) {
        int qg = q0g + w * 4 + qi;
        qp[qi]  = pos[b * SS + qg];
        qsg[qi] = seg[b * SS + qg];
    }

    float mval[4], lval[4], acc[4][8];
    #pragma unroll
    for (int qi = 0; qi < 4; qi++) {
        mval[qi] = -1e30f; lval[qi] = 0.f;
        #pragma unroll
        for (int t = 0; t < 8; t++) acc[qi][t] = 0.f;
    }

    int kend = q0g + 32;
    int kstart = 0;
    { int lo = q0g - (window - 1); if (lo > 0) kstart = lo & ~31; }

    for (int kb = kstart; kb < kend; kb += 32) {
        __syncthreads();
        // load K/V tile (float4)
        for (int t = tid; t < 32 * 64; t += 256) {
            int kk = t >> 6, d4 = t & 63;
            const float* krow = qkv + (size_t)(b * SS + kb + kk) * 4096 + 2048 + kvh * 256;
            float4 kv = *(const float4*)(krow + 4 * d4);
            float4 vv = *(const float4*)(krow + 1024 + 4 * d4);
            *(float4*)(Ks + kk * KPAD + 4 * d4) = kv;
            *(float4*)(Vs + kk * KPAD + 4 * d4) = vv;
        }
        if (tid < 32) { kposs[tid] = pos[b * SS + kb + tid]; ksegs[tid] = seg[b * SS + kb + tid]; }
        __syncthreads();

        int kp = kposs[lane], ks = ksegs[lane];
        const float4* kr4 = (const float4*)(Ks + lane * KPAD);
        const float4* qr4 = (const float4*)(Qs + (w * 4) * 256);
        float dot[4] = {0.f, 0.f, 0.f, 0.f};
        #pragma unroll 4
        for (int d4 = 0; d4 < 64; d4++) {
            float4 kv = kr4[d4];
            float4 q0 = qr4[d4];
            float4 q1 = qr4[64 + d4];
            float4 q2 = qr4[128 + d4];
            float4 q3 = qr4[192 + d4];
            dot[0] += q0.x*kv.x + q0.y*kv.y + q0.z*kv.z + q0.w*kv.w;
            dot[1] += q1.x*kv.x + q1.y*kv.y + q1.z*kv.z + q1.w*kv.w;
            dot[2] += q2.x*kv.x + q2.y*kv.y + q2.z*kv.z + q2.w*kv.w;
            dot[3] += q3.x*kv.x + q3.y*kv.y + q3.z*kv.z + q3.w*kv.w;
        }

        #pragma unroll
        for (int qi = 0; qi < 4; qi++) {
            bool valid = (kp <= qp[qi]) && ((qp[qi] - kp) < window) && (ks == qsg[qi]);
            // q-scale hd^-0.5 = 1/16 folded: 0.02/16 = 0.00125
            float lg = 50.f * tanhf(dot[qi] * 0.00125f);
            lg = valid ? lg : -1e30f;
            float tm = lg;
            #pragma unroll
            for (int o = 16; o; o >>= 1) tm = fmaxf(tm, __shfl_xor_sync(0xffffffffu, tm, o));
            float nm = fmaxf(mval[qi], tm);
            float p = __expf(lg - nm);
            float psum = p;
            #pragma unroll
            for (int o = 16; o; o >>= 1) psum += __shfl_xor_sync(0xffffffffu, psum, o);
            float alpha = __expf(mval[qi] - nm);
            mval[qi] = nm;
            lval[qi] = lval[qi] * alpha + psum;
            #pragma unroll
            for (int t = 0; t < 8; t++) acc[qi][t] *= alpha;
            Ps[(w * 4 + qi) * 32 + lane] = p;
        }
        __syncwarp();

        for (int kk = 0; kk < 32; kk++) {
            float vr[8];
            #pragma unroll
            for (int t = 0; t < 8; t++) vr[t] = Vs[kk * KPAD + lane + 32 * t];
            #pragma unroll
            for (int qi = 0; qi < 4; qi++) {
                float pk = Ps[(w * 4 + qi) * 32 + kk];
                #pragma unroll
                for (int t = 0; t < 8; t++) acc[qi][t] += pk * vr[t];
            }
        }
    }

    // tf32-round outputs: this buffer is the A operand of the O-projection GEMM
    #pragma unroll
    for (int qi = 0; qi < 4; qi++) {
        int qg = q0g + w * 4 + qi;
        float inv = 1.f / lval[qi];
        float* op = out + ((size_t)(b * SS + qg) * NHQ + h) * HD;
        #pragma unroll
        for (int t = 0; t < 8; t++)
            op[lane + 32 * t] = __uint_as_float(f2tf(acc[qi][t] * inv));
    }
}

// ---------------- host-side orchestration ----------------
static void round_pack(const float* in, uint32_t* out, int ncols_src, int ncols_dst, int col0, int n) {
    int n4 = n / 4;
    round_pack_kernel<<<(n4 + 255) / 256, 256>>>((const float4*)in, (uint4*)out,
                                                 ncols_src / 4, ncols_dst / 4, col0 / 4, n4);
}

static void run_layer(const float* pre_attn, const float* post_attn,
                      const float* pre_ffw, const float* post_ffw,
                      const float* wq, const float* wk, const float* wv, const float* wo,
                      const float* wi0, const float* wi1, const float* wom,
                      const int* pos, const int* seg, int window,
                      float* x, float* h, float* qkv,
                      float* att, float* tmp, float* ff, float* ff2,
                      uint32_t* pwqkv, uint32_t* pwo,
                      uint32_t* pwi0, uint32_t* pwi1, uint32_t* pwom) {
    // round + pack weights
    round_pack(wq,  pwqkv, 2048, 4096, 0,    DD * 2048);
    round_pack(wk,  pwqkv, 1024, 4096, 2048, DD * 1024);
    round_pack(wv,  pwqkv, 1024, 4096, 3072, DD * 1024);
    round_pack(wo,  pwo,  DD, DD, 0, NHQ * HD * DD);
    round_pack(wi0, pwi0, FF, FF, 0, DD * FF);
    round_pack(wi1, pwi1, FF, FF, 0, DD * FF);
    round_pack(wom, pwom, DD, DD, 0, FF * DD);

    rms_kernel<<<MM, 256>>>(x, pre_attn, h);
    tf32_gemm<0><<<dim3(4096/128, MM/128), 256, SMEM_GEMM>>>(
        (const uint32_t*)h, pwqkv, qkv, nullptr, MM, 4096, DD, 1.f);
    {
        int tot = MM * 12 * 128;
        rope_merged_kernel<<<(tot + 255)/256, 256>>>(qkv, pos, tot);
    }
    attn_kernel<<<dim3(SS/32, NHQ, BB), 256, ATTN_SMEM_BYTES>>>(qkv, pos, seg, att, window);
    tf32_gemm<0><<<dim3(DD/128, MM/128), 256, SMEM_GEMM>>>(
        (const uint32_t*)att, pwo, tmp, nullptr, MM, DD, NHQ*HD, 1.f);
    rms_add_kernel<<<MM, 256>>>(tmp, post_attn, x);
    rms_kernel<<<MM, 256>>>(x, pre_ffw, h);
    tf32_gemm<0><<<dim3(FF/128, MM/128), 256, SMEM_GEMM>>>(
        (const uint32_t*)h, pwi0, ff, nullptr, MM, FF, DD, 1.f);
    tf32_gemm<1><<<dim3(FF/128, MM/128), 256, SMEM_GEMM>>>(
        (const uint32_t*)h, pwi1, ff2, ff, MM, FF, DD, 1.f);
    tf32_gemm<0><<<dim3(DD/128, MM/128), 256, SMEM_GEMM>>>(
        (const uint32_t*)ff2, pwom, tmp, nullptr, MM, DD, FF, 1.f);
    rms_add_kernel<<<MM, 256>>>(tmp, post_ffw, x);
}

extern "C" void kernel_launch(void* const* d_in, const int* in_sizes, int n_in,
                              void* d_out, int out_size) {
    const float* x_in = (const float*)d_in[0];
    const int* pos    = (const int*)d_in[1];
    const int* seg    = (const int*)d_in[2];
    const float* pre_attn_l  = (const float*)d_in[3];
    const float* post_attn_l = (const float*)d_in[4];
    const float* pre_ffw_l   = (const float*)d_in[5];
    const float* post_ffw_l  = (const float*)d_in[6];
    const float* wq_l  = (const float*)d_in[7];
    const float* wk_l  = (const float*)d_in[8];
    const float* wv_l  = (const float*)d_in[9];
    const float* wo_l  = (const float*)d_in[10];
    const float* wi0_l = (const float*)d_in[11];
    const float* wi1_l = (const float*)d_in[12];
    const float* wom_l = (const float*)d_in[13];
    const float* pre_attn_g  = (const float*)d_in[14];
    const float* post_attn_g = (const float*)d_in[15];
    const float* pre_ffw_g   = (const float*)d_in[16];
    const float* post_ffw_g  = (const float*)d_in[17];
    const float* wq_g  = (const float*)d_in[18];
    const float* wk_g  = (const float*)d_in[19];
    const float* wv_g  = (const float*)d_in[20];
    const float* wo_g  = (const float*)d_in[21];
    const float* wi0_g = (const float*)d_in[22];
    const float* wi1_g = (const float*)d_in[23];
    const float* wom_g = (const float*)d_in[24];

    float *px, *ph, *pqkv, *patt, *ptmp, *pff, *pff2;
    uint32_t *pwqkv, *pwo, *pwi0, *pwi1, *pwom;
    cudaGetSymbolAddress((void**)&px,    g_x);
    cudaGetSymbolAddress((void**)&ph,    g_h);
    cudaGetSymbolAddress((void**)&pqkv,  g_qkv);
    cudaGetSymbolAddress((void**)&patt,  g_att);
    cudaGetSymbolAddress((void**)&ptmp,  g_tmp);
    cudaGetSymbolAddress((void**)&pff,   g_ff);
    cudaGetSymbolAddress((void**)&pff2,  g_ff2);
    cudaGetSymbolAddress((void**)&pwqkv, g_wqkv);
    cudaGetSymbolAddress((void**)&pwo,   g_wo);
    cudaGetSymbolAddress((void**)&pwi0,  g_wi0);
    cudaGetSymbolAddress((void**)&pwi1,  g_wi1);
    cudaGetSymbolAddress((void**)&pwom,  g_wom);

    cudaFuncSetAttribute(attn_kernel, cudaFuncAttributeMaxDynamicSharedMemorySize, ATTN_SMEM_BYTES);
    cudaFuncSetAttribute(tf32_gemm<0>, cudaFuncAttributeMaxDynamicSharedMemorySize, SMEM_GEMM);
    cudaFuncSetAttribute(tf32_gemm<1>, cudaFuncAttributeMaxDynamicSharedMemorySize, SMEM_GEMM);

    int n = MM * DD;
    copy_kernel<<<(n + 255)/256, 256>>>(px, x_in, n);

    run_layer(pre_attn_l, post_attn_l, pre_ffw_l, post_ffw_l,
              wq_l, wk_l, wv_l, wo_l, wi0_l, wi1_l, wom_l,
              pos, seg, /*window=*/1024,
              px, ph, pqkv, patt, ptmp, pff, pff2,
              pwqkv, pwo, pwi0, pwi1, pwom);

    run_layer(pre_attn_g, post_attn_g, pre_ffw_g, post_ffw_g,
              wq_g, wk_g, wv_g, wo_g, wi0_g, wi1_g, wom_g,
              pos, seg, /*window=*/SS,
              px, ph, pqkv, patt, ptmp, pff, pff2,
              pwqkv, pwo, pwi0, pwi1, pwom);

    copy_kernel<<<(n + 255)/256, 256>>>((float*)d_out, px, n);
}

// round 16
// speedup vs baseline: 1.0043x; 1.0043x over previous
#include <cuda_runtime.h>
#include <math.h>
#include <stdint.h>

#define BB 2
#define SS 2048
#define DD 2304
#define NHQ 8
#define NHKV 4
#define HD 256
#define FF 9216
#define MM (BB*SS)   // 4096 rows

// ---------------- persistent scratch (no allocations allowed) ----------------
__device__ float g_x  [MM*DD];
__device__ float g_h  [MM*DD];
__device__ float g_qkv[MM*4096];          // q (0..2047) | k (2048..3071) | v (3072..4095)
__device__ float g_att[MM*NHQ*HD];
__device__ float g_tmp[MM*DD];
__device__ float g_ff [MM*FF];
__device__ float g_ff2[MM*FF];
// pre-rounded (tf32) weights
__device__ uint32_t g_wqkv[DD*4096];
__device__ uint32_t g_wo [NHQ*HD*DD];
__device__ uint32_t g_wi0[DD*FF];
__device__ uint32_t g_wi1[DD*FF];
__device__ uint32_t g_wom[FF*DD];

__device__ __forceinline__ uint32_t f2tf(float x) {
    uint32_t r;
    asm("cvt.rna.tf32.f32 %0, %1;" : "=r"(r) : "f"(x));
    return r;
}

// ---------------- small helpers ----------------
__global__ void copy_kernel(float* __restrict__ dst, const float* __restrict__ src, int n) {
    int i = blockIdx.x * blockDim.x + threadIdx.x;
    if (i < n) dst[i] = src[i];
}

// tf32-round and (optionally) pack into a wider matrix at column offset.
// Works in float4 units. src is [n4/ncols4_src rows, ncols4_src cols4].
__global__ void round_pack_kernel(const float4* __restrict__ in, uint4* __restrict__ out,
                                  int ncols4_src, int ncols4_dst, int col0_4, int n4) {
    int i = blockIdx.x * blockDim.x + threadIdx.x;
    if (i >= n4) return;
    int k = i / ncols4_src, j = i - k * ncols4_src;
    float4 v = in[i];
    uint4 u;
    u.x = f2tf(v.x); u.y = f2tf(v.y); u.z = f2tf(v.z); u.w = f2tf(v.w);
    out[(size_t)k * ncols4_dst + col0_4 + j] = u;
}

// out[row] = tf32_round(in[row] * rsqrt(mean(in^2)+eps) * scale)   (GEMM A operand)
__global__ void rms_kernel(const float* __restrict__ in, const float* __restrict__ scale,
                           float* __restrict__ out) {
    int row = blockIdx.x;
    const float* r = in + (size_t)row * DD;
    float ss = 0.f;
    for (int i = threadIdx.x; i < DD; i += 256) { float v = r[i]; ss += v * v; }
    #pragma unroll
    for (int o = 16; o; o >>= 1) ss += __shfl_xor_sync(0xffffffffu, ss, o);
    __shared__ float red[8];
    if ((threadIdx.x & 31) == 0) red[threadIdx.x >> 5] = ss;
    __syncthreads();
    float tot = red[0]+red[1]+red[2]+red[3]+red[4]+red[5]+red[6]+red[7];
    float rs = rsqrtf(tot / (float)DD + 1e-6f);
    float* o = out + (size_t)row * DD;
    for (int i = threadIdx.x; i < DD; i += 256)
        o[i] = __uint_as_float(f2tf(r[i] * rs * scale[i]));
}

__global__ void rms_add_kernel(const float* __restrict__ a, const float* __restrict__ scale,
                               float* __restrict__ x) {
    int row = blockIdx.x;
    const float* r = a + (size_t)row * DD;
    float ss = 0.f;
    for (int i = threadIdx.x; i < DD; i += 256) { float v = r[i]; ss += v * v; }
    #pragma unroll
    for (int o = 16; o; o >>= 1) ss += __shfl_xor_sync(0xffffffffu, ss, o);
    __shared__ float red[8];
    if ((threadIdx.x & 31) == 0) red[threadIdx.x >> 5] = ss;
    __syncthreads();
    float tot = red[0]+red[1]+red[2]+red[3]+red[4]+red[5]+red[6]+red[7];
    float rs = rsqrtf(tot / (float)DD + 1e-6f);
    float* xo = x + (size_t)row * DD;
    for (int i = threadIdx.x; i < DD; i += 256) xo[i] += r[i] * rs * scale[i];
}

__device__ __forceinline__ float gelu_tanh(float x) {
    float x3 = x * x * x;
    return 0.5f * x * (1.f + tanhf(0.7978845608028654f * (x + 0.044715f * x3)));
}

// ---------------- tf32 tensor-core GEMM, cp.async 3-stage pipeline ----------------
#define GSTAGES 3
#define SMEM_GEMM (GSTAGES * (128*32 + 32*128) * 4)

__device__ __forceinline__ void mma8(float* c, const uint32_t* a, const uint32_t* b) {
    asm volatile("mma.sync.aligned.m16n8k8.row.col.f32.tf32.tf32.f32 "
        "{%0,%1,%2,%3},{%4,%5,%6,%7},{%8,%9},{%0,%1,%2,%3};"
        : "+f"(c[0]), "+f"(c[1]), "+f"(c[2]), "+f"(c[3])
        : "r"(a[0]), "r"(a[1]), "r"(a[2]), "r"(a[3]), "r"(b[0]), "r"(b[1]));
}

template<int MODE>
__global__ void __launch_bounds__(256) tf32_gemm(const uint32_t* __restrict__ A,
                                                 const uint32_t* __restrict__ B,
                                                 float* __restrict__ C,
                                                 const float* __restrict__ aux,
                                                 int M, int N, int K, float alpha) {
    extern __shared__ uint32_t smem_[];
    uint32_t* As = smem_;                          // [GSTAGES][128*32], col ^ 4*(row&7)
    uint32_t* Bs = smem_ + GSTAGES * 128 * 32;     // [GSTAGES][32*128], col ^ 8*(row&3)

    int tid = threadIdx.x;
    int lane = tid & 31;
    int warp = tid >> 5;
    int wm = warp & 3;
    int wn = warp >> 2;
    int g = lane >> 2;
    int t = lane & 3;

    int m0 = blockIdx.y * 128;
    int n0 = blockIdx.x * 128;

    int arow = tid >> 3;            // 0..31
    int acol = (tid & 7) * 4;       // 0..28
    int brow = tid >> 5;            // 0..7
    int bcol = (tid & 31) * 4;      // 0..124

    float acc[2][8][4];
    #pragma unroll
    for (int mi = 0; mi < 2; mi++)
        #pragma unroll
        for (int ni = 0; ni < 8; ni++)
            #pragma unroll
            for (int j = 0; j < 4; j++) acc[mi][ni][j] = 0.f;

    auto load_stage = [&](int k0, int s) {
        uint32_t* Ad = As + s * (128 * 32);
        uint32_t* Bd = Bs + s * (32 * 128);
        #pragma unroll
        for (int p = 0; p < 4; p++) {
            int r = arow + p * 32;
            int sc = acol ^ (4 * (r & 7));
            uint32_t d = (uint32_t)__cvta_generic_to_shared(Ad + r * 32 + sc);
            asm volatile("cp.async.cg.shared.global [%0], [%1], 16;\n"
                         :: "r"(d), "l"(A + (size_t)(m0 + r) * K + k0 + acol));
        }
        #pragma unroll
        for (int p = 0; p < 4; p++) {
            int r = brow + p * 8;
            int sc = bcol ^ (8 * (r & 3));
            uint32_t d = (uint32_t)__cvta_generic_to_shared(Bd + r * 128 + sc);
            asm volatile("cp.async.cg.shared.global [%0], [%1], 16;\n"
                         :: "r"(d), "l"(B + (size_t)(k0 + r) * N + n0 + bcol));
        }
    };

    int nk = K / 32;
    load_stage(0, 0);
    asm volatile("cp.async.commit_group;\n" ::);
    load_stage(32, 1);
    asm volatile("cp.async.commit_group;\n" ::);

    for (int ki = 0; ki < nk; ki++) {
        asm volatile("cp.async.wait_group 1;\n" ::);
        __syncthreads();
        if (ki + 2 < nk) load_stage((ki + 2) * 32, (ki + 2) % GSTAGES);
        asm volatile("cp.async.commit_group;\n" ::);

        const uint32_t* Ac = As + (ki % GSTAGES) * (128 * 32);
        const uint32_t* Bc = Bs + (ki % GSTAGES) * (32 * 128);

        #pragma unroll
        for (int kk = 0; kk < 32; kk += 8) {
            uint32_t af[2][4], bf[8][2];
            #pragma unroll
            for (int mi = 0; mi < 2; mi++) {
                int r0 = wm * 32 + mi * 16 + g;
                int c0 = (kk + t) ^ (4 * g);
                int c1 = (kk + t + 4) ^ (4 * g);
                af[mi][0] = Ac[r0 * 32 + c0];
                af[mi][1] = Ac[(r0 + 8) * 32 + c0];
                af[mi][2] = Ac[r0 * 32 + c1];
                af[mi][3] = Ac[(r0 + 8) * 32 + c1];
            }
            #pragma unroll
            for (int ni = 0; ni < 8; ni++) {
                int n = wn * 64 + ni * 8 + g;
                bf[ni][0] = Bc[(kk + t) * 128 + (n ^ (8 * t))];
                bf[ni][1] = Bc[(kk + t + 4) * 128 + (n ^ (8 * t))];
            }
            #pragma unroll
            for (int mi = 0; mi < 2; mi++)
                #pragma unroll
                for (int ni = 0; ni < 8; ni++)
                    mma8(acc[mi][ni], af[mi], bf[ni]);
        }
    }

    #pragma unroll
    for (int mi = 0; mi < 2; mi++) {
        #pragma unroll
        for (int ni = 0; ni < 8; ni++) {
            int row = m0 + wm * 32 + mi * 16 + g;
            int col = n0 + wn * 64 + ni * 8 + 2 * t;
            size_t i0 = (size_t)row * N + col;
            size_t i1 = (size_t)(row + 8) * N + col;
            if (MODE == 0) {
                float2 v0 = make_float2(acc[mi][ni][0] * alpha, acc[mi][ni][1] * alpha);
                float2 v1 = make_float2(acc[mi][ni][2] * alpha, acc[mi][ni][3] * alpha);
                *(float2*)(C + i0) = v0;
                *(float2*)(C + i1) = v1;
            } else {
                float2 a0 = *(const float2*)(aux + i0);
                float2 a1 = *(const float2*)(aux + i1);
                float2 v0 = make_float2(__uint_as_float(f2tf(gelu_tanh(a0.x) * acc[mi][ni][0])),
                                        __uint_as_float(f2tf(gelu_tanh(a0.y) * acc[mi][ni][1])));
                float2 v1 = make_float2(__uint_as_float(f2tf(gelu_tanh(a1.x) * acc[mi][ni][2])),
                                        __uint_as_float(f2tf(gelu_tanh(a1.y) * acc[mi][ni][3])));
                *(float2*)(C + i0) = v0;
                *(float2*)(C + i1) = v1;
            }
        }
    }
}

// ---------------- RoPE on merged qkv (q heads 0..7 at col h*256, k heads at 2048+h*256) ----------------
__global__ void rope_merged_kernel(float* __restrict__ qkv, const int* __restrict__ positions, int total) {
    int idx = blockIdx.x * blockDim.x + threadIdx.x;
    if (idx >= total) return;
    int i = idx & 127;
    int hh = (idx >> 7) % 12;                // 0..7 = q heads, 8..11 = k heads
    int row = idx / (128 * 12);              // 0..MM-1
    int s = row % SS, b = row / SS;
    int p = positions[b * SS + s];
    double f = exp2(-(double)i * (13.287712379549449 / 128.0));
    double ang = (double)p * f;
    double sd, cd;
    sincos(ang, &sd, &cd);
    float sn = (float)sd, cs = (float)cd;
    int col = (hh < 8) ? hh * 256 : 2048 + (hh - 8) * 256;
    float* base = qkv + (size_t)row * 4096 + col;
    float x1 = base[i], x2 = base[128 + i];
    base[i]       = x1 * cs - x2 * sn;
    base[128 + i] = x2 * cs + x1 * sn;
}

// ---------------- attention: online softmax, softcap, causal+window+segment ----------------
// KPAD=260: float4 row loads are conflict-free (8-lane phases x 4 words cover all 32 banks),
// and rows stay 16B-aligned (260*4 = 1040 = 65*16).
#define KPAD 260
#define ATTN_SMEM_FLOATS (32*256 + 32*KPAD + 32*KPAD + 8*4*32 + 64)
#define ATTN_SMEM_BYTES (ATTN_SMEM_FLOATS * 4)

__global__ void __launch_bounds__(256) attn_kernel(const float* __restrict__ qkv,
                                                   const int* __restrict__ pos,
                                                   const int* __restrict__ seg,
                                                   float* __restrict__ out,
                                                   int window) {
    extern __shared__ float sm[];
    float* Qs = sm;                      // [32][256]
    float* Ks = Qs + 32 * 256;           // [32][KPAD]
    float* Vs = Ks + 32 * KPAD;          // [32][KPAD]
    float* Ps = Vs + 32 * KPAD;          // [8][4][32]
    int* kposs = (int*)(Ps + 8 * 4 * 32);
    int* ksegs = kposs + 32;

    int b = blockIdx.z, h = blockIdx.y, qt = blockIdx.x;
    int kvh = h / (NHQ / NHKV);
    int tid = threadIdx.x, w = tid >> 5, lane = tid & 31;
    int q0g = qt * 32;

    // load Q tile (float4)
    for (int t = tid; t < 32 * 64; t += 256) {
        int lq = t >> 6, d4 = t & 63;
        *(float4*)(Qs + lq * 256 + 4 * d4) =
            *(const float4*)(qkv + (size_t)(b * SS + q0g + lq) * 4096 + h * 256 + 4 * d4);
    }

    int qp[4], qsg[4];
    #pragma unroll
    for (int qi = 0; qi < 4; qi++) {
        int qg = q0g + w * 4 + qi;
        qp[qi]  = pos[b * SS + qg];
        qsg[qi] = seg[b * SS + qg];
    }

    float mval[4], lval[4], acc[4][8];
    #pragma unroll
    for (int qi = 0; qi < 4; qi++) {
        mval[qi] = -1e30f; lval[qi] = 0.f;
        #pragma unroll
        for (int t = 0; t < 8; t++) acc[qi][t] = 0.f;
    }

    int kend = q0g + 32;
    int kstart = 0;
    { int lo = q0g - (window - 1); if (lo > 0) kstart = lo & ~31; }

    for (int kb = kstart; kb < kend; kb += 32) {
        __syncthreads();
        // load K/V tile (float4)
        for (int t = tid; t < 32 * 64; t += 256) {
            int kk = t >> 6, d4 = t & 63;
            const float* krow = qkv + (size_t)(b * SS + kb + kk) * 4096 + 2048 + kvh * 256;
            float4 kv = *(const float4*)(krow + 4 * d4);
            float4 vv = *(const float4*)(krow + 1024 + 4 * d4);
            *(float4*)(Ks + kk * KPAD + 4 * d4) = kv;
            *(float4*)(Vs + kk * KPAD + 4 * d4) = vv;
        }
        if (tid < 32) { kposs[tid] = pos[b * SS + kb + tid]; ksegs[tid] = seg[b * SS + kb + tid]; }
        __syncthreads();

        int kp = kposs[lane], ks = ksegs[lane];
        const float4* kr4 = (const float4*)(Ks + lane * KPAD);
        const float4* qr4 = (const float4*)(Qs + (w * 4) * 256);
        float dot[4] = {0.f, 0.f, 0.f, 0.f};
        #pragma unroll 4
        for (int d4 = 0; d4 < 64; d4++) {
            float4 kv = kr4[d4];
            float4 q0 = qr4[d4];
            float4 q1 = qr4[64 + d4];
            float4 q2 = qr4[128 + d4];
            float4 q3 = qr4[192 + d4];
            dot[0] += q0.x*kv.x + q0.y*kv.y + q0.z*kv.z + q0.w*kv.w;
            dot[1] += q1.x*kv.x + q1.y*kv.y + q1.z*kv.z + q1.w*kv.w;
            dot[2] += q2.x*kv.x + q2.y*kv.y + q2.z*kv.z + q2.w*kv.w;
            dot[3] += q3.x*kv.x + q3.y*kv.y + q3.z*kv.z + q3.w*kv.w;
        }

        #pragma unroll
        for (int qi = 0; qi < 4; qi++) {
            bool valid = (kp <= qp[qi]) && ((qp[qi] - kp) < window) && (ks == qsg[qi]);
            // q-scale hd^-0.5 = 1/16 folded: 0.02/16 = 0.00125
            float lg = 50.f * tanhf(dot[qi] * 0.00125f);
            lg = valid ? lg : -1e30f;
            float tm = lg;
            #pragma unroll
            for (int o = 16; o; o >>= 1) tm = fmaxf(tm, __shfl_xor_sync(0xffffffffu, tm, o));
            float nm = fmaxf(mval[qi], tm);
            float p = __expf(lg - nm);
            float psum = p;
            #pragma unroll
            for (int o = 16; o; o >>= 1) psum += __shfl_xor_sync(0xffffffffu, psum, o);
            float alpha = __expf(mval[qi] - nm);
            mval[qi] = nm;
            lval[qi] = lval[qi] * alpha + psum;
            #pragma unroll
            for (int t = 0; t < 8; t++) acc[qi][t] *= alpha;
            Ps[(w * 4 + qi) * 32 + lane] = p;
        }
        __syncwarp();

        for (int kk = 0; kk < 32; kk++) {
            float vr[8];
            #pragma unroll
            for (int t = 0; t < 8; t++) vr[t] = Vs[kk * KPAD + lane + 32 * t];
            #pragma unroll
            for (int qi = 0; qi < 4; qi++) {
                float pk = Ps[(w * 4 + qi) * 32 + kk];
                #pragma unroll
                for (int t = 0; t < 8; t++) acc[qi][t] += pk * vr[t];
            }
        }
    }

    // tf32-round outputs: this buffer is the A operand of the O-projection GEMM
    #pragma unroll
    for (int qi = 0; qi < 4; qi++) {
        int qg = q0g + w * 4 + qi;
        float inv = 1.f / lval[qi];
        float* op = out + ((size_t)(b * SS + qg) * NHQ + h) * HD;
        #pragma unroll
        for (int t = 0; t < 8; t++)
            op[lane + 32 * t] = __uint_as_float(f2tf(acc[qi][t] * inv));
    }
}

// ---------------- host-side orchestration ----------------
static void round_pack(const float* in, uint32_t* out, int ncols_src, int ncols_dst, int col0, int n) {
    int n4 = n / 4;
    round_pack_kernel<<<(n4 + 255) / 256, 256>>>((const float4*)in, (uint4*)out,
                                                 ncols_src / 4, ncols_dst / 4, col0 / 4, n4);
}

static void run_layer(const float* pre_attn, const float* post_attn,
                      const float* pre_ffw, const float* post_ffw,
                      const float* wq, const float* wk, const float* wv, const float* wo,
                      const float* wi0, const float* wi1, const float* wom,
                      const int* pos, const int* seg, int window,
                      float* x, float* h, float* qkv,
                      float* att, float* tmp, float* ff, float* ff2,
                      uint32_t* pwqkv, uint32_t* pwo,
                      uint32_t* pwi0, uint32_t* pwi1, uint32_t* pwom) {
    // round + pack weights
    round_pack(wq,  pwqkv, 2048, 4096, 0,    DD * 2048);
    round_pack(wk,  pwqkv, 1024, 4096, 2048, DD * 1024);
    round_pack(wv,  pwqkv, 1024, 4096, 3072, DD * 1024);
    round_pack(wo,  pwo,  DD, DD, 0, NHQ * HD * DD);
    round_pack(wi0, pwi0, FF, FF, 0, DD * FF);
    round_pack(wi1, pwi1, FF, FF, 0, DD * FF);
    round_pack(wom, pwom, DD, DD, 0, FF * DD);

    rms_kernel<<<MM, 256>>>(x, pre_attn, h);
    tf32_gemm<0><<<dim3(4096/128, MM/128), 256, SMEM_GEMM>>>(
        (const uint32_t*)h, pwqkv, qkv, nullptr, MM, 4096, DD, 1.f);
    {
        int tot = MM * 12 * 128;
        rope_merged_kernel<<<(tot + 255)/256, 256>>>(qkv, pos, tot);
    }
    attn_kernel<<<dim3(SS/32, NHQ, BB), 256, ATTN_SMEM_BYTES>>>(qkv, pos, seg, att, window);
    tf32_gemm<0><<<dim3(DD/128, MM/128), 256, SMEM_GEMM>>>(
        (const uint32_t*)att, pwo, tmp, nullptr, MM, DD, NHQ*HD, 1.f);
    rms_add_kernel<<<MM, 256>>>(tmp, post_attn, x);
    rms_kernel<<<MM, 256>>>(x, pre_ffw, h);
    tf32_gemm<0><<<dim3(FF/128, MM/128), 256, SMEM_GEMM>>>(
        (const uint32_t*)h, pwi0, ff, nullptr, MM, FF, DD, 1.f);
    tf32_gemm<1><<<dim3(FF/128, MM/128), 256, SMEM_GEMM>>>(
        (const uint32_t*)h, pwi1, ff2, ff, MM, FF, DD, 1.f);
    tf32_gemm<0><<<dim3(DD/128, MM/128), 256, SMEM_GEMM>>>(
        (const uint32_t*)ff2, pwom, tmp, nullptr, MM, DD, FF, 1.f);
    rms_add_kernel<<<MM, 256>>>(tmp, post_ffw, x);
}

extern "C" void kernel_launch(void* const* d_in, const int* in_sizes, int n_in,
                              void* d_out, int out_size) {
    const float* x_in = (const float*)d_in[0];
    const int* pos    = (const int*)d_in[1];
    const int* seg    = (const int*)d_in[2];
    const float* pre_attn_l  = (const float*)d_in[3];
    const float* post_attn_l = (const float*)d_in[4];
    const float* pre_ffw_l   = (const float*)d_in[5];
    const float* post_ffw_l  = (const float*)d_in[6];
    const float* wq_l  = (const float*)d_in[7];
    const float* wk_l  = (const float*)d_in[8];
    const float* wv_l  = (const float*)d_in[9];
    const float* wo_l  = (const float*)d_in[10];
    const float* wi0_l = (const float*)d_in[11];
    const float* wi1_l = (const float*)d_in[12];
    const float* wom_l = (const float*)d_in[13];
    const float* pre_attn_g  = (const float*)d_in[14];
    const float* post_attn_g = (const float*)d_in[15];
    const float* pre_ffw_g   = (const float*)d_in[16];
    const float* post_ffw_g  = (const float*)d_in[17];
    const float* wq_g  = (const float*)d_in[18];
    const float* wk_g  = (const float*)d_in[19];
    const float* wv_g  = (const float*)d_in[20];
    const float* wo_g  = (const float*)d_in[21];
    const float* wi0_g = (const float*)d_in[22];
    const float* wi1_g = (const float*)d_in[23];
    const float* wom_g = (const float*)d_in[24];

    float *px, *ph, *pqkv, *patt, *ptmp, *pff, *pff2;
    uint32_t *pwqkv, *pwo, *pwi0, *pwi1, *pwom;
    cudaGetSymbolAddress((void**)&px,    g_x);
    cudaGetSymbolAddress((void**)&ph,    g_h);
    cudaGetSymbolAddress((void**)&pqkv,  g_qkv);
    cudaGetSymbolAddress((void**)&patt,  g_att);
    cudaGetSymbolAddress((void**)&ptmp,  g_tmp);
    cudaGetSymbolAddress((void**)&pff,   g_ff);
    cudaGetSymbolAddress((void**)&pff2,  g_ff2);
    cudaGetSymbolAddress((void**)&pwqkv, g_wqkv);
    cudaGetSymbolAddress((void**)&pwo,   g_wo);
    cudaGetSymbolAddress((void**)&pwi0,  g_wi0);
    cudaGetSymbolAddress((void**)&pwi1,  g_wi1);
    cudaGetSymbolAddress((void**)&pwom,  g_wom);

    cudaFuncSetAttribute(attn_kernel, cudaFuncAttributeMaxDynamicSharedMemorySize, ATTN_SMEM_BYTES);
    cudaFuncSetAttribute(tf32_gemm<0>, cudaFuncAttributeMaxDynamicSharedMemorySize, SMEM_GEMM);
    cudaFuncSetAttribute(tf32_gemm<1>, cudaFuncAttributeMaxDynamicSharedMemorySize, SMEM_GEMM);

    int n = MM * DD;
    copy_kernel<<<(n + 255)/256, 256>>>(px, x_in, n);

    run_layer(pre_attn_l, post_attn_l, pre_ffw_l, post_ffw_l,
              wq_l, wk_l, wv_l, wo_l, wi0_l, wi1_l, wom_l,
              pos, seg, /*window=*/1024,
              px, ph, pqkv, patt, ptmp, pff, pff2,
              pwqkv, pwo, pwi0, pwi1, pwom);

    run_layer(pre_attn_g, post_attn_g, pre_ffw_g, post_ffw_g,
              wq_g, wk_g, wv_g, wo_g, wi0_g, wi1_g, wom_g,
              pos, seg, /*window=*/SS,
              px, ph, pqkv, patt, ptmp, pff, pff2,
              pwqkv, pwo, pwi0, pwi1, pwom);

    copy_kernel<<<(n + 255)/256, 256>>>((float*)d_out, px, n);
}